// round 13
// baseline (speedup 1.0000x reference)
#include <cuda_runtime.h>
#include <cuda_fp16.h>
#include <cstdint>

#define NTOK 8192
#define DIM 4096
#define ODIM 4096
#define NEXP 8
#define RNK 16
#define KLORA 128
#define SCALING_F 2.0f
#define MAXTHR 0.125f

// ---------------- device scratch --------------------------------------------
__device__ float g_w[NTOK * NEXP];
__device__ __half g_xh[(size_t)NTOK * DIM];
__device__ __half g_Wh[(size_t)ODIM * DIM];
__device__ __half g_Ah[KLORA * DIM];
__device__ __half g_Bc[ODIM * KLORA];
__device__ __half g_gh[NTOK * KLORA];

// ---------------- PTX helpers -----------------------------------------------
__device__ __forceinline__ uint32_t smem_u32(const void* p) {
    uint32_t a;
    asm("{ .reg .u64 t; cvta.to.shared.u64 t, %1; cvt.u32.u64 %0, t; }" : "=r"(a) : "l"(p));
    return a;
}
__device__ __forceinline__ void cp16(uint32_t dst, const void* src) {
    asm volatile("cp.async.cg.shared.global [%0], [%1], 16;" :: "r"(dst), "l"(src));
}
#define CP_COMMIT() asm volatile("cp.async.commit_group;" ::: "memory")
#define CP_WAIT2()  asm volatile("cp.async.wait_group 2;" ::: "memory")

__device__ __forceinline__ void ldsm4(uint32_t& r0, uint32_t& r1, uint32_t& r2, uint32_t& r3,
                                      uint32_t addr) {
    asm volatile("ldmatrix.sync.aligned.m8n8.x4.shared.b16 {%0,%1,%2,%3}, [%4];"
                 : "=r"(r0), "=r"(r1), "=r"(r2), "=r"(r3) : "r"(addr));
}
__device__ __forceinline__ void mma16816(float* d, const uint32_t* a, const uint32_t* b) {
    asm volatile("mma.sync.aligned.m16n8k16.row.col.f32.f16.f16.f32 "
                 "{%0,%1,%2,%3}, {%4,%5,%6,%7}, {%8,%9}, {%0,%1,%2,%3};"
                 : "+f"(d[0]), "+f"(d[1]), "+f"(d[2]), "+f"(d[3])
                 : "r"(a[0]), "r"(a[1]), "r"(a[2]), "r"(a[3]), "r"(b[0]), "r"(b[1]));
}

// ---------------- fused prep kernel ------------------------------------------
#define NB_XG (NTOK / 4)                            // 2048
#define NB_WS (ODIM * DIM / 4 / 256)                // 16384
#define NB_AS (KLORA * DIM / 4 / 256)               // 512
#define NB_BC (ODIM * KLORA / 4 / 256)              // 512
#define NB_TOTAL (NB_XG + NB_WS + NB_AS + NB_BC)

__global__ __launch_bounds__(256)
void prep_kernel(const float* __restrict__ x,
                 const float* __restrict__ Wb,
                 const float* __restrict__ Wg,
                 const float* __restrict__ Wt,
                 const float* __restrict__ bt,
                 const float* __restrict__ Aw,
                 const float* __restrict__ Bw) {
    int bid = blockIdx.x;
    int tid = threadIdx.x;

    if (bid < NB_XG) {
        int n0 = bid * 4;
        int r = tid >> 6;
        int c = tid & 63;
        int row = n0 + r;
        const float4* xrow = (const float4*)x + (size_t)row * (DIM / 4);
        float acc[9];
#pragma unroll
        for (int i = 0; i < 9; i++) acc[i] = 0.f;

#pragma unroll 8
        for (int j = 0; j < 16; j++) {
            int idx = c + j * 64;
            float4 v = xrow[idx];
#pragma unroll
            for (int e = 0; e < NEXP; e++) {
                float4 wv = ((const float4*)Wg)[e * (DIM / 4) + idx];
                acc[e] = fmaf(v.x, wv.x, fmaf(v.y, wv.y, fmaf(v.z, wv.z, fmaf(v.w, wv.w, acc[e]))));
            }
            float4 wt = ((const float4*)Wt)[idx];
            acc[8] = fmaf(v.x, wt.x, fmaf(v.y, wt.y, fmaf(v.z, wt.z, fmaf(v.w, wt.w, acc[8]))));
            size_t o = (size_t)row * (DIM / 4) + idx;
            ((__half2*)g_xh)[2 * o]     = __half2(__float2half_rn(v.x), __float2half_rn(v.y));
            ((__half2*)g_xh)[2 * o + 1] = __half2(__float2half_rn(v.z), __float2half_rn(v.w));
        }
#pragma unroll
        for (int i = 0; i < 9; i++)
#pragma unroll
            for (int off = 16; off; off >>= 1)
                acc[i] += __shfl_down_sync(0xffffffffu, acc[i], off);
        __shared__ float sred[8][9];
        int warp = tid >> 5, lane = tid & 31;
        if (lane == 0)
#pragma unroll
            for (int i = 0; i < 9; i++) sred[warp][i] = acc[i];
        __syncthreads();
        if (tid < 4) {
            int t = tid;
            float v[9];
#pragma unroll
            for (int i = 0; i < 9; i++) v[i] = sred[2 * t][i] + sred[2 * t + 1][i];
            float mx = v[0];
#pragma unroll
            for (int e = 1; e < NEXP; e++) mx = fmaxf(mx, v[e]);
            float se = 0.f, gate[NEXP];
#pragma unroll
            for (int e = 0; e < NEXP; e++) { gate[e] = expf(v[e] - mx); se += gate[e]; }
            float inv = 1.f / se;
            float thr = MAXTHR / (1.f + expf(-(v[8] + bt[0])));
            float w[NEXP]; float ws = 0.f;
#pragma unroll
            for (int e = 0; e < NEXP; e++) {
                float a = gate[e] * inv - thr;
                w[e] = (a >= 0.f) ? a : 0.f;
                ws += w[e];
            }
            if (ws == 0.f) ws = 1.f;
            float sc = SCALING_F / ws;
#pragma unroll
            for (int e = 0; e < NEXP; e++) g_w[(n0 + t) * NEXP + e] = w[e] * sc;
        }
        return;
    }
    bid -= NB_XG;

    if (bid < NB_WS) {
        int i = bid * 256 + tid;
        float4 v = ((const float4*)Wb)[i];
        ((__half2*)g_Wh)[2 * i]     = __half2(__float2half_rn(v.x), __float2half_rn(v.y));
        ((__half2*)g_Wh)[2 * i + 1] = __half2(__float2half_rn(v.z), __float2half_rn(v.w));
        return;
    }
    bid -= NB_WS;

    if (bid < NB_AS) {
        int i = bid * 256 + tid;
        float4 v = ((const float4*)Aw)[i];
        ((__half2*)g_Ah)[2 * i]     = __half2(__float2half_rn(v.x), __float2half_rn(v.y));
        ((__half2*)g_Ah)[2 * i + 1] = __half2(__float2half_rn(v.z), __float2half_rn(v.w));
        return;
    }
    bid -= NB_AS;

    {
        int i = bid * 256 + tid;
        int idx = i * 4;
        int o = idx >> 7, k = idx & 127;
        int e = k >> 4, r = k & 15;
        const float* src = Bw + ((size_t)e * ODIM + o) * RNK + r;
        float4 v = *(const float4*)src;
        ((__half2*)g_Bc)[2 * i]     = __half2(__float2half_rn(v.x), __float2half_rn(v.y));
        ((__half2*)g_Bc)[2 * i + 1] = __half2(__float2half_rn(v.z), __float2half_rn(v.w));
        return;
    }
}

// ---------------- HMMA GEMM (single fp16 pass) --------------------------------
// smem rows of 32 fp16 (64B), row stride 80B => conflict-free ldmatrix
#define RS 80
#define NSTG 4

template <int MODE, int BM, int BN, int NT>
__device__ __forceinline__ void issue_chunk(uint32_t sbase, int stage, int chunk,
                                            int m0, int n0, int tid) {
    constexpr int AB = BM * RS;
    constexpr int BB = BN * RS;
    constexpr int STAGE_B = AB + BB;
    const __half *Ah, *Bh;
    int sA, sB, rA, rB, kcol;
    if (MODE == 1 && chunk >= 128) {
        kcol = (chunk - 128) * 32;
        Ah = g_gh; sA = KLORA; rA = m0;
        Bh = g_Bc; sB = KLORA; rB = n0;
    } else if (MODE == 1) {
        kcol = chunk * 32;
        Ah = g_xh; sA = DIM; rA = m0;
        Bh = g_Wh; sB = DIM; rB = n0;
    } else {
        kcol = chunk * 32;
        Ah = g_xh; sA = DIM; rA = m0;
        Bh = g_Ah; sB = DIM; rB = 0;
    }
    uint32_t base = sbase + stage * STAGE_B;
#pragma unroll
    for (int c = tid; c < BM * 4; c += NT) {
        int row = c >> 2, k16 = c & 3;
        uint32_t dof = row * RS + k16 * 16;
        cp16(base + dof, Ah + (size_t)(rA + row) * sA + kcol + k16 * 8);
    }
#pragma unroll
    for (int c = tid; c < BN * 4; c += NT) {
        int row = c >> 2, k16 = c & 3;
        uint32_t dof = row * RS + k16 * 16;
        cp16(base + AB + dof, Bh + (size_t)(rB + row) * sB + kcol + k16 * 8);
    }
}

template <int MT>
__device__ __forceinline__ void load_frags(uint32_t aB, uint32_t bB, int s,
                                           uint32_t ah[MT][4], uint32_t bh[8][2]) {
#pragma unroll
    for (int mt = 0; mt < MT; mt++)
        ldsm4(ah[mt][0], ah[mt][1], ah[mt][2], ah[mt][3], aB + mt * 16 * RS + s * 32);
#pragma unroll
    for (int p = 0; p < 4; p++)
        ldsm4(bh[2 * p][0], bh[2 * p][1], bh[2 * p + 1][0], bh[2 * p + 1][1],
              bB + p * 16 * RS + s * 32);
}

template <int BM, int BN, int MT>
__device__ __forceinline__ void compute_stage(uint32_t sbase, int stage, int wm, int wn64,
                                              uint32_t aLane, uint32_t bLane,
                                              float acc[MT][8][4]) {
    constexpr int AB = BM * RS;
    constexpr int BB = BN * RS;
    constexpr int STAGE_B = AB + BB;
    uint32_t base = sbase + stage * STAGE_B;
    uint32_t aB = base + wm * (MT * 16) * RS + aLane;
    uint32_t bB = base + AB + wn64 * 64 * RS + bLane;

    uint32_t ah[2][MT][4], bh[2][8][2];
    load_frags<MT>(aB, bB, 0, ah[0], bh[0]);
#pragma unroll
    for (int s = 0; s < 2; s++) {
        if (s == 0) load_frags<MT>(aB, bB, 1, ah[1], bh[1]);
#pragma unroll
        for (int mt = 0; mt < MT; mt++)
#pragma unroll
            for (int nt = 0; nt < 8; nt++)
                mma16816(acc[mt][nt], ah[s][mt], bh[s][nt]);
    }
}

// MODE 1: main, BM=256, BN=128, NT=256, 1 CTA/SM (8 warps, 4x2, warp tile 64x64).
// MODE 0: h-gemm, BM=64, BN=128, NT=128, 2 CTAs/SM (4 warps, 2x2, warp tile 32x64).
template <int MODE, int BM, int BN, int NT, int MAXB>
__global__ __launch_bounds__(NT, MAXB)
void hmma_gemm_kernel(const float* __restrict__ bb, float* __restrict__ out) {
    constexpr int NCHUNK = (MODE == 1) ? 132 : 128;
    constexpr int NWM = (MODE == 1) ? 4 : 2;        // M-slabs of warps
    constexpr int MT = BM / (16 * NWM);             // main: 4, h: 2
    extern __shared__ char smem[];
    uint32_t sbase = smem_u32(smem);

    int tid = threadIdx.x;
    int wid = tid >> 5, lane = tid & 31;
    int wm = wid & (NWM - 1);
    int wn64 = wid / NWM;

    int m0, n0;
    if (MODE == 1) {
        int bid = blockIdx.x;
        int sg = bid >> 6, idx = bid & 63;      // supergroups: 8 m-tiles x 8 n-tiles
        int mg = sg & 3, ng = sg >> 2;          // 32/8=4 m-groups, 32/8=4 n-groups
        m0 = (mg * 8 + (idx & 7)) * 256;
        n0 = (ng * 8 + (idx >> 3)) * 128;
    } else {
        m0 = blockIdx.x * BM; n0 = 0;
    }

    uint32_t aLane = (uint32_t)((lane & 15) * RS + (lane >> 4) * 16);
    uint32_t bLane = (uint32_t)(((lane & 7) + ((lane >> 4) & 1) * 8) * RS + ((lane >> 3) & 1) * 16);

    float acc[MT][8][4];
#pragma unroll
    for (int a = 0; a < MT; a++)
#pragma unroll
        for (int b = 0; b < 8; b++)
#pragma unroll
            for (int c = 0; c < 4; c++) acc[a][b][c] = 0.f;

    issue_chunk<MODE, BM, BN, NT>(sbase, 0, 0, m0, n0, tid); CP_COMMIT();
    issue_chunk<MODE, BM, BN, NT>(sbase, 1, 1, m0, n0, tid); CP_COMMIT();
    issue_chunk<MODE, BM, BN, NT>(sbase, 2, 2, m0, n0, tid); CP_COMMIT();

#pragma unroll 1
    for (int i = 0; i < NCHUNK; i++) {
        CP_WAIT2();
        __syncthreads();
        if (i + 3 < NCHUNK)
            issue_chunk<MODE, BM, BN, NT>(sbase, (i + 3) & (NSTG - 1), i + 3, m0, n0, tid);
        CP_COMMIT();
        compute_stage<BM, BN, MT>(sbase, i & (NSTG - 1), wm, wn64, aLane, bLane, acc);
    }

    // ---- epilogue ----
    int g = lane >> 2, t = lane & 3;
    if (MODE == 1) {
#pragma unroll
        for (int mt = 0; mt < MT; mt++) {
            int r0 = m0 + wm * (MT * 16) + mt * 16 + g;
#pragma unroll
            for (int nt = 0; nt < 8; nt++) {
                int cc = n0 + wn64 * 64 + nt * 8 + t * 2;
                float2 bv = *(const float2*)(bb + cc);
                float2 v0 = make_float2(acc[mt][nt][0] + bv.x, acc[mt][nt][1] + bv.y);
                float2 v1 = make_float2(acc[mt][nt][2] + bv.x, acc[mt][nt][3] + bv.y);
                *(float2*)(out + (size_t)r0 * ODIM + cc) = v0;
                *(float2*)(out + (size_t)(r0 + 8) * ODIM + cc) = v1;
            }
        }
    } else {
#pragma unroll
        for (int mt = 0; mt < MT; mt++) {
            int r0 = m0 + wm * (MT * 16) + mt * 16 + g;
            int r1 = r0 + 8;
#pragma unroll
            for (int nt = 0; nt < 8; nt++) {
                int cc = wn64 * 64 + nt * 8 + t * 2;
                int e = (wn64 * 64 + nt * 8) >> 4;
                float w0 = g_w[r0 * NEXP + e];
                float w1 = g_w[r1 * NEXP + e];
                *(__half2*)(g_gh + (size_t)r0 * KLORA + cc) =
                    __half2(__float2half_rn(acc[mt][nt][0] * w0), __float2half_rn(acc[mt][nt][1] * w0));
                *(__half2*)(g_gh + (size_t)r1 * KLORA + cc) =
                    __half2(__float2half_rn(acc[mt][nt][2] * w1), __float2half_rn(acc[mt][nt][3] * w1));
            }
        }
    }
}

// ---------------------------------------------------------------------------
extern "C" void kernel_launch(void* const* d_in, const int* in_sizes, int n_in,
                              void* d_out, int out_size) {
    const float* x  = (const float*)d_in[0];
    const float* Wb = (const float*)d_in[1];
    const float* bb = (const float*)d_in[2];
    const float* Wg = (const float*)d_in[3];
    const float* Wt = (const float*)d_in[4];
    const float* bt = (const float*)d_in[5];
    const float* Aw = (const float*)d_in[6];
    const float* Bw = (const float*)d_in[7];
    float* out = (float*)d_out;

    constexpr int SMEM_MAIN = NSTG * (256 * RS + 128 * RS);  // 122880, 1 CTA/SM
    constexpr int SMEM_H    = NSTG * (64 * RS + 128 * RS);   // 61440, 2 CTAs/SM
    cudaFuncSetAttribute(hmma_gemm_kernel<1, 256, 128, 256, 1>, cudaFuncAttributeMaxDynamicSharedMemorySize, SMEM_MAIN);
    cudaFuncSetAttribute(hmma_gemm_kernel<0, 64, 128, 128, 2>, cudaFuncAttributeMaxDynamicSharedMemorySize, SMEM_H);

    prep_kernel<<<NB_TOTAL, 256>>>(x, Wb, Wg, Wt, bt, Aw, Bw);
    hmma_gemm_kernel<0, 64, 128, 128, 2><<<NTOK / 64, 128, SMEM_H>>>(nullptr, nullptr);
    hmma_gemm_kernel<1, 256, 128, 256, 1><<<(NTOK / 256) * (ODIM / 128), 256, SMEM_MAIN>>>(bb, out);
}

// round 14
// speedup vs baseline: 1.3892x; 1.3892x over previous
#include <cuda_runtime.h>
#include <cuda_fp16.h>
#include <cstdint>

#define NTOK 8192
#define DIM 4096
#define ODIM 4096
#define NEXP 8
#define RNK 16
#define KLORA 128
#define SCALING_F 2.0f
#define MAXTHR 0.125f

// ---------------- device scratch --------------------------------------------
__device__ float g_w[NTOK * NEXP];
__device__ __half g_xh[(size_t)NTOK * DIM];
__device__ __half g_Wh[(size_t)ODIM * DIM];
__device__ __half g_Ah[KLORA * DIM];
__device__ __half g_Bc[ODIM * KLORA];
__device__ __half g_gh[NTOK * KLORA];

// ---------------- PTX helpers -----------------------------------------------
__device__ __forceinline__ uint32_t smem_u32(const void* p) {
    uint32_t a;
    asm("{ .reg .u64 t; cvta.to.shared.u64 t, %1; cvt.u32.u64 %0, t; }" : "=r"(a) : "l"(p));
    return a;
}
__device__ __forceinline__ void cp16(uint32_t dst, const void* src) {
    asm volatile("cp.async.cg.shared.global [%0], [%1], 16;" :: "r"(dst), "l"(src));
}
#define CP_COMMIT() asm volatile("cp.async.commit_group;" ::: "memory")
#define CP_WAIT2()  asm volatile("cp.async.wait_group 2;" ::: "memory")

__device__ __forceinline__ void ldsm4(uint32_t& r0, uint32_t& r1, uint32_t& r2, uint32_t& r3,
                                      uint32_t addr) {
    asm volatile("ldmatrix.sync.aligned.m8n8.x4.shared.b16 {%0,%1,%2,%3}, [%4];"
                 : "=r"(r0), "=r"(r1), "=r"(r2), "=r"(r3) : "r"(addr));
}
__device__ __forceinline__ void mma16816(float* d, const uint32_t* a, const uint32_t* b) {
    asm volatile("mma.sync.aligned.m16n8k16.row.col.f32.f16.f16.f32 "
                 "{%0,%1,%2,%3}, {%4,%5,%6,%7}, {%8,%9}, {%0,%1,%2,%3};"
                 : "+f"(d[0]), "+f"(d[1]), "+f"(d[2]), "+f"(d[3])
                 : "r"(a[0]), "r"(a[1]), "r"(a[2]), "r"(a[3]), "r"(b[0]), "r"(b[1]));
}

// ---------------- fused prep kernel ------------------------------------------
// streaming sections: 4 float4 per thread (MLP=4)
#define NB_XG (NTOK / 4)                               // 2048
#define NB_WS (ODIM * DIM / 4 / 256 / 4)               // 4096
#define NB_AS (KLORA * DIM / 4 / 256 / 4)              // 128
#define NB_BC (ODIM * KLORA / 4 / 256 / 4)             // 128
#define NB_TOTAL (NB_XG + NB_WS + NB_AS + NB_BC)

__global__ __launch_bounds__(256)
void prep_kernel(const float* __restrict__ x,
                 const float* __restrict__ Wb,
                 const float* __restrict__ Wg,
                 const float* __restrict__ Wt,
                 const float* __restrict__ bt,
                 const float* __restrict__ Aw,
                 const float* __restrict__ Bw) {
    int bid = blockIdx.x;
    int tid = threadIdx.x;

    if (bid < NB_XG) {
        // ---- x convert + gate: 4 rows, 64 threads per row ----
        int n0 = bid * 4;
        int r = tid >> 6;
        int c = tid & 63;
        int row = n0 + r;
        const float4* xrow = (const float4*)x + (size_t)row * (DIM / 4);
        float acc[9];
#pragma unroll
        for (int i = 0; i < 9; i++) acc[i] = 0.f;

#pragma unroll 8
        for (int j = 0; j < 16; j++) {
            int idx = c + j * 64;
            float4 v = xrow[idx];
#pragma unroll
            for (int e = 0; e < NEXP; e++) {
                float4 wv = ((const float4*)Wg)[e * (DIM / 4) + idx];
                acc[e] = fmaf(v.x, wv.x, fmaf(v.y, wv.y, fmaf(v.z, wv.z, fmaf(v.w, wv.w, acc[e]))));
            }
            float4 wt = ((const float4*)Wt)[idx];
            acc[8] = fmaf(v.x, wt.x, fmaf(v.y, wt.y, fmaf(v.z, wt.z, fmaf(v.w, wt.w, acc[8]))));
            size_t o = (size_t)row * (DIM / 4) + idx;
            ((__half2*)g_xh)[2 * o]     = __half2(__float2half_rn(v.x), __float2half_rn(v.y));
            ((__half2*)g_xh)[2 * o + 1] = __half2(__float2half_rn(v.z), __float2half_rn(v.w));
        }
#pragma unroll
        for (int i = 0; i < 9; i++)
#pragma unroll
            for (int off = 16; off; off >>= 1)
                acc[i] += __shfl_down_sync(0xffffffffu, acc[i], off);
        __shared__ float sred[8][9];
        int warp = tid >> 5, lane = tid & 31;
        if (lane == 0)
#pragma unroll
            for (int i = 0; i < 9; i++) sred[warp][i] = acc[i];
        __syncthreads();
        if (tid < 4) {
            int t = tid;
            float v[9];
#pragma unroll
            for (int i = 0; i < 9; i++) v[i] = sred[2 * t][i] + sred[2 * t + 1][i];
            float mx = v[0];
#pragma unroll
            for (int e = 1; e < NEXP; e++) mx = fmaxf(mx, v[e]);
            float se = 0.f, gate[NEXP];
#pragma unroll
            for (int e = 0; e < NEXP; e++) { gate[e] = expf(v[e] - mx); se += gate[e]; }
            float inv = 1.f / se;
            float thr = MAXTHR / (1.f + expf(-(v[8] + bt[0])));
            float w[NEXP]; float ws = 0.f;
#pragma unroll
            for (int e = 0; e < NEXP; e++) {
                float a = gate[e] * inv - thr;
                w[e] = (a >= 0.f) ? a : 0.f;
                ws += w[e];
            }
            if (ws == 0.f) ws = 1.f;
            float sc = SCALING_F / ws;
#pragma unroll
            for (int e = 0; e < NEXP; e++) g_w[(n0 + t) * NEXP + e] = w[e] * sc;
        }
        return;
    }
    bid -= NB_XG;

    if (bid < NB_WS) {
        // ---- W -> fp16, 4 float4 per thread ----
        int i0 = bid * 1024 + tid;
        float4 v[4];
#pragma unroll
        for (int k = 0; k < 4; k++) v[k] = ((const float4*)Wb)[i0 + k * 256];
#pragma unroll
        for (int k = 0; k < 4; k++) {
            int i = i0 + k * 256;
            ((__half2*)g_Wh)[2 * i]     = __half2(__float2half_rn(v[k].x), __float2half_rn(v[k].y));
            ((__half2*)g_Wh)[2 * i + 1] = __half2(__float2half_rn(v[k].z), __float2half_rn(v[k].w));
        }
        return;
    }
    bid -= NB_WS;

    if (bid < NB_AS) {
        // ---- A_w -> fp16, 4 float4 per thread ----
        int i0 = bid * 1024 + tid;
        float4 v[4];
#pragma unroll
        for (int k = 0; k < 4; k++) v[k] = ((const float4*)Aw)[i0 + k * 256];
#pragma unroll
        for (int k = 0; k < 4; k++) {
            int i = i0 + k * 256;
            ((__half2*)g_Ah)[2 * i]     = __half2(__float2half_rn(v[k].x), __float2half_rn(v[k].y));
            ((__half2*)g_Ah)[2 * i + 1] = __half2(__float2half_rn(v[k].z), __float2half_rn(v[k].w));
        }
        return;
    }
    bid -= NB_AS;

    {
        // ---- B_w reorder -> [O,128] fp16, 4 float4 per thread ----
        int i0 = bid * 1024 + tid;
        float4 v[4];
#pragma unroll
        for (int k = 0; k < 4; k++) {
            int i = i0 + k * 256;
            int idx = i * 4;
            int o = idx >> 7, kk = idx & 127;
            int e = kk >> 4, r = kk & 15;
            v[k] = *(const float4*)(Bw + ((size_t)e * ODIM + o) * RNK + r);
        }
#pragma unroll
        for (int k = 0; k < 4; k++) {
            int i = i0 + k * 256;
            ((__half2*)g_Bc)[2 * i]     = __half2(__float2half_rn(v[k].x), __float2half_rn(v[k].y));
            ((__half2*)g_Bc)[2 * i + 1] = __half2(__float2half_rn(v[k].z), __float2half_rn(v[k].w));
        }
        return;
    }
}

// ---------------- HMMA GEMM (single fp16 pass) --------------------------------
// smem rows of 32 fp16 (64B), row stride 80B => conflict-free ldmatrix
#define RS 80
#define NSTG 4

template <int MODE, int BM, int BN, int NT>
__device__ __forceinline__ void issue_chunk(uint32_t sbase, int stage, int chunk,
                                            int m0, int n0, int tid) {
    constexpr int AB = BM * RS;
    constexpr int BB = BN * RS;
    constexpr int STAGE_B = AB + BB;
    const __half *Ah, *Bh;
    int sA, sB, rA, rB, kcol;
    if (MODE == 1 && chunk >= 128) {
        kcol = (chunk - 128) * 32;
        Ah = g_gh; sA = KLORA; rA = m0;
        Bh = g_Bc; sB = KLORA; rB = n0;
    } else if (MODE == 1) {
        kcol = chunk * 32;
        Ah = g_xh; sA = DIM; rA = m0;
        Bh = g_Wh; sB = DIM; rB = n0;
    } else {
        kcol = chunk * 32;
        Ah = g_xh; sA = DIM; rA = m0;
        Bh = g_Ah; sB = DIM; rB = 0;
    }
    uint32_t base = sbase + stage * STAGE_B;
#pragma unroll
    for (int c = tid; c < BM * 4; c += NT) {
        int row = c >> 2, k16 = c & 3;
        uint32_t dof = row * RS + k16 * 16;
        cp16(base + dof, Ah + (size_t)(rA + row) * sA + kcol + k16 * 8);
    }
#pragma unroll
    for (int c = tid; c < BN * 4; c += NT) {
        int row = c >> 2, k16 = c & 3;
        uint32_t dof = row * RS + k16 * 16;
        cp16(base + AB + dof, Bh + (size_t)(rB + row) * sB + kcol + k16 * 8);
    }
}

template <int MT>
__device__ __forceinline__ void load_frags(uint32_t aB, uint32_t bB, int s,
                                           uint32_t ah[MT][4], uint32_t bh[8][2]) {
#pragma unroll
    for (int mt = 0; mt < MT; mt++)
        ldsm4(ah[mt][0], ah[mt][1], ah[mt][2], ah[mt][3], aB + mt * 16 * RS + s * 32);
#pragma unroll
    for (int p = 0; p < 4; p++)
        ldsm4(bh[2 * p][0], bh[2 * p][1], bh[2 * p + 1][0], bh[2 * p + 1][1],
              bB + p * 16 * RS + s * 32);
}

template <int BM, int BN, int MT>
__device__ __forceinline__ void compute_stage(uint32_t sbase, int stage, int wm, int wn64,
                                              uint32_t aLane, uint32_t bLane,
                                              float acc[MT][8][4]) {
    constexpr int AB = BM * RS;
    constexpr int BB = BN * RS;
    constexpr int STAGE_B = AB + BB;
    uint32_t base = sbase + stage * STAGE_B;
    uint32_t aB = base + wm * (MT * 16) * RS + aLane;
    uint32_t bB = base + AB + wn64 * 64 * RS + bLane;

    uint32_t ah[2][MT][4], bh[2][8][2];
    load_frags<MT>(aB, bB, 0, ah[0], bh[0]);
#pragma unroll
    for (int s = 0; s < 2; s++) {
        if (s == 0) load_frags<MT>(aB, bB, 1, ah[1], bh[1]);
#pragma unroll
        for (int mt = 0; mt < MT; mt++)
#pragma unroll
            for (int nt = 0; nt < 8; nt++)
                mma16816(acc[mt][nt], ah[s][mt], bh[s][nt]);
    }
}

// MODE 1: main, BM=128, BN=128, NT=128, 2 CTAs/SM. MODE 0: h-gemm, BM=64.
template <int MODE, int BM, int BN, int NT>
__global__ __launch_bounds__(NT, 2)
void hmma_gemm_kernel(const float* __restrict__ bb, float* __restrict__ out) {
    constexpr int NCHUNK = (MODE == 1) ? 132 : 128;
    constexpr int MT = BM / 32;     // main: 4, h: 2
    extern __shared__ char smem[];
    uint32_t sbase = smem_u32(smem);

    int tid = threadIdx.x;
    int wid = tid >> 5, lane = tid & 31;
    int wm = wid & 1;
    int wn64 = wid >> 1;

    int m0, n0;
    if (MODE == 1) {
        int bid = blockIdx.x;
        int sg = bid >> 6, idx = bid & 63;      // 8x8 supergroups of 128x128 tiles
        int mg = sg & 7, ng = sg >> 3;
        m0 = (mg * 8 + (idx & 7)) * 128;
        n0 = (ng * 8 + (idx >> 3)) * 128;
    } else {
        m0 = blockIdx.x * BM; n0 = 0;
    }

    uint32_t aLane = (uint32_t)((lane & 15) * RS + (lane >> 4) * 16);
    uint32_t bLane = (uint32_t)(((lane & 7) + ((lane >> 4) & 1) * 8) * RS + ((lane >> 3) & 1) * 16);

    float acc[MT][8][4];
#pragma unroll
    for (int a = 0; a < MT; a++)
#pragma unroll
        for (int b = 0; b < 8; b++)
#pragma unroll
            for (int c = 0; c < 4; c++) acc[a][b][c] = 0.f;

    issue_chunk<MODE, BM, BN, NT>(sbase, 0, 0, m0, n0, tid); CP_COMMIT();
    issue_chunk<MODE, BM, BN, NT>(sbase, 1, 1, m0, n0, tid); CP_COMMIT();
    issue_chunk<MODE, BM, BN, NT>(sbase, 2, 2, m0, n0, tid); CP_COMMIT();

#pragma unroll 1
    for (int i = 0; i < NCHUNK; i++) {
        CP_WAIT2();
        __syncthreads();
        if (i + 3 < NCHUNK)
            issue_chunk<MODE, BM, BN, NT>(sbase, (i + 3) & (NSTG - 1), i + 3, m0, n0, tid);
        CP_COMMIT();
        compute_stage<BM, BN, MT>(sbase, i & (NSTG - 1), wm, wn64, aLane, bLane, acc);
    }

    // ---- epilogue ----
    int g = lane >> 2, t = lane & 3;
    if (MODE == 1) {
#pragma unroll
        for (int mt = 0; mt < MT; mt++) {
            int r0 = m0 + wm * (MT * 16) + mt * 16 + g;
#pragma unroll
            for (int nt = 0; nt < 8; nt++) {
                int cc = n0 + wn64 * 64 + nt * 8 + t * 2;
                float2 bv = *(const float2*)(bb + cc);
                float2 v0 = make_float2(acc[mt][nt][0] + bv.x, acc[mt][nt][1] + bv.y);
                float2 v1 = make_float2(acc[mt][nt][2] + bv.x, acc[mt][nt][3] + bv.y);
                *(float2*)(out + (size_t)r0 * ODIM + cc) = v0;
                *(float2*)(out + (size_t)(r0 + 8) * ODIM + cc) = v1;
            }
        }
    } else {
#pragma unroll
        for (int mt = 0; mt < MT; mt++) {
            int r0 = m0 + wm * (MT * 16) + mt * 16 + g;
            int r1 = r0 + 8;
#pragma unroll
            for (int nt = 0; nt < 8; nt++) {
                int cc = wn64 * 64 + nt * 8 + t * 2;
                int e = (wn64 * 64 + nt * 8) >> 4;
                float w0 = g_w[r0 * NEXP + e];
                float w1 = g_w[r1 * NEXP + e];
                *(__half2*)(g_gh + (size_t)r0 * KLORA + cc) =
                    __half2(__float2half_rn(acc[mt][nt][0] * w0), __float2half_rn(acc[mt][nt][1] * w0));
                *(__half2*)(g_gh + (size_t)r1 * KLORA + cc) =
                    __half2(__float2half_rn(acc[mt][nt][2] * w1), __float2half_rn(acc[mt][nt][3] * w1));
            }
        }
    }
}

// ---------------------------------------------------------------------------
extern "C" void kernel_launch(void* const* d_in, const int* in_sizes, int n_in,
                              void* d_out, int out_size) {
    const float* x  = (const float*)d_in[0];
    const float* Wb = (const float*)d_in[1];
    const float* bb = (const float*)d_in[2];
    const float* Wg = (const float*)d_in[3];
    const float* Wt = (const float*)d_in[4];
    const float* bt = (const float*)d_in[5];
    const float* Aw = (const float*)d_in[6];
    const float* Bw = (const float*)d_in[7];
    float* out = (float*)d_out;

    constexpr int SMEM_MAIN = NSTG * (128 * RS + 128 * RS);  // 81920 -> 2 CTAs/SM
    constexpr int SMEM_H    = NSTG * (64 * RS + 128 * RS);   // 61440 -> 2 CTAs/SM
    cudaFuncSetAttribute(hmma_gemm_kernel<1, 128, 128, 128>, cudaFuncAttributeMaxDynamicSharedMemorySize, SMEM_MAIN);
    cudaFuncSetAttribute(hmma_gemm_kernel<0, 64, 128, 128>, cudaFuncAttributeMaxDynamicSharedMemorySize, SMEM_H);

    prep_kernel<<<NB_TOTAL, 256>>>(x, Wb, Wg, Wt, bt, Aw, Bw);
    hmma_gemm_kernel<0, 64, 128, 128><<<NTOK / 64, 128, SMEM_H>>>(nullptr, nullptr);
    hmma_gemm_kernel<1, 128, 128, 128><<<(NTOK / 128) * (ODIM / 128), 128, SMEM_MAIN>>>(bb, out);
}